// round 1
// baseline (speedup 1.0000x reference)
#include <cuda_runtime.h>
#include <cuda_bf16.h>
#include <math_constants.h>

// Problem constants (fixed by the reference)
#define D 1024
#define NKEYS 32768
#define TOPK 10

// Scratch (no allocations allowed -> device globals)
__device__ float g_q[D];
__device__ float g_scores[NKEYS];

// ---------------------------------------------------------------------------
// Kernel 1: q = Wq @ query + bq      (q[j] = dot(Wq[j,:], query) + bq[j])
// 32 blocks x 256 threads; 8 warps/block, each warp does 4 rows.
// ---------------------------------------------------------------------------
__global__ void __launch_bounds__(256) qproj_kernel(const float* __restrict__ Wq,
                                                    const float* __restrict__ query,
                                                    const float* __restrict__ bq) {
    __shared__ float4 qs[D / 4];
    int tid = threadIdx.x;
    // load query into smem (256 float4 = 1024 floats)
    qs[tid] = ((const float4*)query)[tid];
    __syncthreads();

    int warp = tid >> 5, lane = tid & 31;
    int rowBase = blockIdx.x * 32 + warp * 4;
#pragma unroll
    for (int r = 0; r < 4; r++) {
        int row = rowBase + r;
        const float4* wp = (const float4*)(Wq + (size_t)row * D);
        float acc = 0.f;
#pragma unroll
        for (int j = 0; j < 8; j++) {
            float4 a = wp[lane + 32 * j];
            float4 b = qs[lane + 32 * j];
            acc += a.x * b.x + a.y * b.y + a.z * b.z + a.w * b.w;
        }
#pragma unroll
        for (int o = 16; o; o >>= 1) acc += __shfl_down_sync(0xFFFFFFFFu, acc, o);
        if (lane == 0) g_q[row] = acc + bq[row];
    }
}

// ---------------------------------------------------------------------------
// Kernel 2: scores = keys @ q   (the 128 MB streaming matvec — HBM-bound)
// 1024 blocks x 256 threads; 8 warps/block, each warp does 4 rows.
// ---------------------------------------------------------------------------
__global__ void __launch_bounds__(256) scores_kernel(const float* __restrict__ keys) {
    __shared__ float4 qs[D / 4];
    int tid = threadIdx.x;
    qs[tid] = ((const float4*)g_q)[tid];
    __syncthreads();

    int warp = tid >> 5, lane = tid & 31;
    int rowBase = blockIdx.x * 32 + warp * 4;
#pragma unroll
    for (int r = 0; r < 4; r++) {
        int row = rowBase + r;
        const float4* kp = (const float4*)(keys + (size_t)row * D);
        float acc = 0.f;
#pragma unroll
        for (int j = 0; j < 8; j++) {
            float4 a = kp[lane + 32 * j];
            float4 b = qs[lane + 32 * j];
            acc += a.x * b.x + a.y * b.y + a.z * b.z + a.w * b.w;
        }
#pragma unroll
        for (int o = 16; o; o >>= 1) acc += __shfl_down_sync(0xFFFFFFFFu, acc, o);
        if (lane == 0) g_scores[row] = acc;
    }
}

// ---------------------------------------------------------------------------
// Kernel 3: softmax constants + top-10 + gather, one 1024-thread block.
// Dynamic smem: scores[32768] + reduce scratch (1024 f + 1024 i).
// Output layout: [retrieved_values (10*1024 floats), top_w (10 floats)]
// ---------------------------------------------------------------------------
__global__ void __launch_bounds__(1024) topk_gather_kernel(const float* __restrict__ values,
                                                           float* __restrict__ out) {
    extern __shared__ float sm[];
    float* s  = sm;                       // NKEYS
    float* rv = sm + NKEYS;               // 1024
    int*   ri = (int*)(rv + 1024);        // 1024
    __shared__ int   top_idx[TOPK];
    __shared__ float top_val[TOPK];

    const int tid = threadIdx.x;
    const float inv = 0.03125f;           // 1/sqrt(1024)

    // Load scores into smem
#pragma unroll
    for (int i = tid; i < NKEYS; i += 1024) s[i] = g_scores[i];
    __syncthreads();

    // --- global max ---
    float m = -CUDART_INF_F;
#pragma unroll
    for (int i = tid; i < NKEYS; i += 1024) m = fmaxf(m, s[i]);
    rv[tid] = m;
    __syncthreads();
    for (int o = 512; o > 0; o >>= 1) {
        if (tid < o) rv[tid] = fmaxf(rv[tid], rv[tid + o]);
        __syncthreads();
    }
    const float smax = rv[0];
    __syncthreads();

    // --- Z = sum exp((s - smax)/sqrt(d)) ---
    float z = 0.f;
#pragma unroll
    for (int i = tid; i < NKEYS; i += 1024) z += expf((s[i] - smax) * inv);
    rv[tid] = z;
    __syncthreads();
    for (int o = 512; o > 0; o >>= 1) {
        if (tid < o) rv[tid] += rv[tid + o];
        __syncthreads();
    }
    const float Z = rv[0];
    __syncthreads();

    // --- iterative top-10 argmax (tie -> lower index, matching top_k) ---
    for (int r = 0; r < TOPK; r++) {
        float bm = -CUDART_INF_F;
        int bi = 0x7FFFFFFF;
        for (int i = tid; i < NKEYS; i += 1024) {
            float v = s[i];
            if (v > bm || (v == bm && i < bi)) { bm = v; bi = i; }
        }
        rv[tid] = bm;
        ri[tid] = bi;
        __syncthreads();
        for (int o = 512; o > 0; o >>= 1) {
            if (tid < o) {
                float v2 = rv[tid + o];
                int   i2 = ri[tid + o];
                if (v2 > rv[tid] || (v2 == rv[tid] && i2 < ri[tid])) {
                    rv[tid] = v2;
                    ri[tid] = i2;
                }
            }
            __syncthreads();
        }
        if (tid == 0) {
            top_idx[r] = ri[0];
            top_val[r] = rv[0];
            s[ri[0]] = -CUDART_INF_F;     // exclude for next round
        }
        __syncthreads();
    }

    // --- gather values rows ---
    for (int r = 0; r < TOPK; r++) {
        const float4* src = (const float4*)(values + (size_t)top_idx[r] * D);
        float4* dst = (float4*)(out + (size_t)r * D);
        if (tid < D / 4) dst[tid] = src[tid];
    }
    // --- weights ---
    if (tid < TOPK) {
        out[TOPK * D + tid] = expf((top_val[tid] - smax) * inv) / Z;
    }
}

// ---------------------------------------------------------------------------
// Launch
// ---------------------------------------------------------------------------
extern "C" void kernel_launch(void* const* d_in, const int* in_sizes, int n_in,
                              void* d_out, int out_size) {
    const float* query  = (const float*)d_in[0];
    const float* keys   = (const float*)d_in[1];
    const float* values = (const float*)d_in[2];
    const float* Wq     = (const float*)d_in[3];
    const float* bq     = (const float*)d_in[4];
    // d_in[5] is k (=10, compile-time constant here)
    float* out = (float*)d_out;

    static bool attr_set = false;
    const int smem_bytes = NKEYS * 4 + 1024 * 4 + 1024 * 4;   // 139264
    if (!attr_set) {
        cudaFuncSetAttribute(topk_gather_kernel,
                             cudaFuncAttributeMaxDynamicSharedMemorySize, smem_bytes);
        attr_set = true;
    }

    qproj_kernel<<<32, 256>>>(Wq, query, bq);
    scores_kernel<<<1024, 256>>>(keys);
    topk_gather_kernel<<<1, 1024, smem_bytes>>>(values, out);
}

// round 2
// speedup vs baseline: 1.7273x; 1.7273x over previous
#include <cuda_runtime.h>
#include <cuda_bf16.h>
#include <math_constants.h>

#define D 1024
#define NKEYS 32768
#define TOPK 10
#define NGROUPS 1024            // top-k groups: element e belongs to group e & 1023

// Scratch (no allocations allowed -> device globals)
__device__ float g_q[D];
__device__ float g_scores[NKEYS];

// ---------------------------------------------------------------------------
// Kernel 1: q = Wq @ query + bq. 128 blocks x 256 thr, warp-per-row (1024 rows)
// ---------------------------------------------------------------------------
__global__ void __launch_bounds__(256) qproj_kernel(const float* __restrict__ Wq,
                                                    const float* __restrict__ query,
                                                    const float* __restrict__ bq) {
    __shared__ float4 qs[D / 4];
    int tid = threadIdx.x;
    qs[tid] = ((const float4*)query)[tid];
    __syncthreads();

    int warp = tid >> 5, lane = tid & 31;
    int row = blockIdx.x * 8 + warp;
    const float4* wp = (const float4*)(Wq + (size_t)row * D);
    float acc = 0.f;
#pragma unroll
    for (int j = 0; j < 8; j++) {
        float4 a = wp[lane + 32 * j];
        float4 b = qs[lane + 32 * j];
        acc += a.x * b.x + a.y * b.y + a.z * b.z + a.w * b.w;
    }
#pragma unroll
    for (int o = 16; o; o >>= 1) acc += __shfl_down_sync(0xFFFFFFFFu, acc, o);
    if (lane == 0) g_q[row] = acc + bq[row];
}

// ---------------------------------------------------------------------------
// Kernel 2: scores = keys @ q  (128 MB stream, HBM roofline target)
// 1024 blocks x 256 thr; 8 warps/block, each warp 4 rows.
// ---------------------------------------------------------------------------
__global__ void __launch_bounds__(256) scores_kernel(const float* __restrict__ keys) {
    __shared__ float4 qs[D / 4];
    int tid = threadIdx.x;
    qs[tid] = ((const float4*)g_q)[tid];
    __syncthreads();

    int warp = tid >> 5, lane = tid & 31;
    int rowBase = blockIdx.x * 32 + warp * 4;
#pragma unroll
    for (int r = 0; r < 4; r++) {
        int row = rowBase + r;
        const float4* kp = (const float4*)(keys + (size_t)row * D);
        float acc = 0.f;
#pragma unroll
        for (int j = 0; j < 8; j++) {
            float4 a = kp[lane + 32 * j];
            float4 b = qs[lane + 32 * j];
            acc += a.x * b.x + a.y * b.y + a.z * b.z + a.w * b.w;
        }
#pragma unroll
        for (int o = 16; o; o >>= 1) acc += __shfl_down_sync(0xFFFFFFFFu, acc, o);
        if (lane == 0) g_scores[row] = acc;
    }
}

// ---------------------------------------------------------------------------
// Kernel 3: softmax Z + top-10 (group-argmax scheme) + gather. 1 block x 1024.
// Group g (= tid) owns elements {g, g+1024, ..., g+31*1024} — conflict-free smem.
// No max-subtraction: scores/32 is tiny, softmax is shift-invariant anyway.
// Output: [retrieved_values (10*1024 f32), top_w (10 f32)]
// ---------------------------------------------------------------------------
__global__ void __launch_bounds__(1024) topk_gather_kernel(const float* __restrict__ values,
                                                           float* __restrict__ out) {
    extern __shared__ float s[];          // NKEYS floats (128 KB)
    __shared__ float gmax[NGROUPS];
    __shared__ int   gidx[NGROUPS];
    __shared__ float wv[32];
    __shared__ int   wi[32];
    __shared__ float zpart[32];
    __shared__ float sZ;
    __shared__ float top_val[TOPK];
    __shared__ int   top_idx[TOPK];
    __shared__ float sBestV;
    __shared__ int   sBestI;

    const int tid  = threadIdx.x;
    const int warp = tid >> 5, lane = tid & 31;
    const float inv = 0.03125f;           // 1/sqrt(1024)

    // --- single pass: stage scores, exp-sum, per-group argmax ---
    float z = 0.f, gm = -CUDART_INF_F;
    int   gi = 0x7FFFFFFF;
#pragma unroll
    for (int j = 0; j < NKEYS / NGROUPS; j++) {
        int i = tid + NGROUPS * j;
        float v = g_scores[i];
        s[i] = v;
        z += expf(v * inv);
        if (v > gm) { gm = v; gi = i; }   // ascending i -> first occurrence kept
    }
    gmax[tid] = gm;
    gidx[tid] = gi;

    // Z reduction: warp shuffles then warp 0
#pragma unroll
    for (int o = 16; o; o >>= 1) z += __shfl_down_sync(0xFFFFFFFFu, z, o);
    if (lane == 0) zpart[warp] = z;
    __syncthreads();
    if (warp == 0) {
        float zz = zpart[lane];
#pragma unroll
        for (int o = 16; o; o >>= 1) zz += __shfl_down_sync(0xFFFFFFFFu, zz, o);
        if (lane == 0) sZ = zz;
    }
    __syncthreads();

    // --- 10 rounds of argmax over the 1024 group maxima ---
    for (int r = 0; r < TOPK; r++) {
        float v = gmax[tid];
        int   i = gidx[tid];
#pragma unroll
        for (int o = 16; o; o >>= 1) {
            float ov = __shfl_down_sync(0xFFFFFFFFu, v, o);
            int   oi = __shfl_down_sync(0xFFFFFFFFu, i, o);
            if (ov > v || (ov == v && oi < i)) { v = ov; i = oi; }
        }
        if (lane == 0) { wv[warp] = v; wi[warp] = i; }
        __syncthreads();
        if (warp == 0) {
            float v2 = wv[lane];
            int   i2 = wi[lane];
#pragma unroll
            for (int o = 16; o; o >>= 1) {
                float ov = __shfl_down_sync(0xFFFFFFFFu, v2, o);
                int   oi = __shfl_down_sync(0xFFFFFFFFu, i2, o);
                if (ov > v2 || (ov == v2 && oi < i2)) { v2 = ov; i2 = oi; }
            }
            if (lane == 0) {
                sBestV = v2; sBestI = i2;
                top_val[r] = v2; top_idx[r] = i2;
            }
        }
        __syncthreads();
        // owner of the winning group removes the winner and recomputes its max
        int bi = sBestI;
        if (tid == (bi & (NGROUPS - 1))) {
            s[bi] = -CUDART_INF_F;
            float m2 = -CUDART_INF_F;
            int   i2 = 0x7FFFFFFF;
#pragma unroll
            for (int j = 0; j < NKEYS / NGROUPS; j++) {
                int i = tid + NGROUPS * j;
                float v3 = s[i];
                if (v3 > m2) { m2 = v3; i2 = i; }
            }
            gmax[tid] = m2;
            gidx[tid] = i2;
        }
        __syncthreads();
    }

    // --- gather the 10 value rows (2560 float4, all threads cooperate) ---
    const float Z = sZ;
#pragma unroll
    for (int f = tid; f < TOPK * (D / 4); f += 1024) {
        int r = f >> 8;                   // f / 256
        int c = f & 255;
        ((float4*)(out + (size_t)r * D))[c] =
            ((const float4*)(values + (size_t)top_idx[r] * D))[c];
    }
    if (tid < TOPK) {
        out[TOPK * D + tid] = expf(top_val[tid] * inv) / Z;
    }
}

// ---------------------------------------------------------------------------
extern "C" void kernel_launch(void* const* d_in, const int* in_sizes, int n_in,
                              void* d_out, int out_size) {
    const float* query  = (const float*)d_in[0];
    const float* keys   = (const float*)d_in[1];
    const float* values = (const float*)d_in[2];
    const float* Wq     = (const float*)d_in[3];
    const float* bq     = (const float*)d_in[4];
    float* out = (float*)d_out;

    static bool attr_set = false;
    const int smem_bytes = NKEYS * 4;     // 131072
    if (!attr_set) {
        cudaFuncSetAttribute(topk_gather_kernel,
                             cudaFuncAttributeMaxDynamicSharedMemorySize, smem_bytes);
        attr_set = true;
    }

    qproj_kernel<<<128, 256>>>(Wq, query, bq);
    scores_kernel<<<1024, 256>>>(keys);
    topk_gather_kernel<<<1, 1024, smem_bytes>>>(values, out);
}